// round 3
// baseline (speedup 1.0000x reference)
#include <cuda_runtime.h>
#include <cuda_bf16.h>

#define NN 50000
#define EE 500000
#define GG 128
#define SCAN_B 512
#define NBLK ((NN + SCAN_B - 1) / SCAN_B)   // 98

// ---------------- scratch (static device allocations) ----------------
__device__ float g_deg[NN];
__device__ float g_dinv[NN];
__device__ int   g_count[NN];
__device__ int   g_rowstart[NN + 1];
__device__ int   g_cursor[NN];
__device__ int   g_part[NBLK];
__device__ int   g_esrc[EE];
__device__ float g_ew[EE];

__device__ float g_P0[NN * 128];
__device__ float g_P1[NN * 128];
__device__ float g_P2[NN * 128];
__device__ float g_H1[NN * 128];
__device__ float g_H2[NN * 64];
__device__ float g_H3[NN * 32];
__device__ float g_pool[GG * 32];
__device__ float g_cntg[GG];

// ---------------- preprocessing ----------------
__global__ void zero_kernel() {
    int i = blockIdx.x * blockDim.x + threadIdx.x;
    if (i < NN) { g_deg[i] = 0.f; g_count[i] = 0; }
    if (i < GG * 32) g_pool[i] = 0.f;
    if (i < GG) g_cntg[i] = 0.f;
}

__global__ void edge_deg_kernel(const int* __restrict__ src, const int* __restrict__ dst,
                                const float* __restrict__ ea) {
    int e = blockIdx.x * blockDim.x + threadIdx.x;
    if (e >= EE) return;
    atomicAdd(&g_deg[src[e]], ea[e]);
    atomicAdd(&g_count[dst[e]], 1);
}

__global__ void dinv_kernel() {
    int i = blockIdx.x * blockDim.x + threadIdx.x;
    if (i >= NN) return;
    float d = g_deg[i];
    g_dinv[i] = (d > 0.f) ? rsqrtf(d) : 0.f;
}

__global__ void scan1_kernel() {
    __shared__ int s[SCAN_B];
    int t = threadIdx.x;
    int i = blockIdx.x * SCAN_B + t;
    int v = (i < NN) ? g_count[i] : 0;
    s[t] = v;
    __syncthreads();
    for (int off = 1; off < SCAN_B; off <<= 1) {
        int add = (t >= off) ? s[t - off] : 0;
        __syncthreads();
        s[t] += add;
        __syncthreads();
    }
    if (i < NN) g_rowstart[i] = s[t] - v;   // exclusive within block
    if (t == SCAN_B - 1) g_part[blockIdx.x] = s[t];
}

__global__ void scan2_kernel() {
    __shared__ int s[128];
    int t = threadIdx.x;
    int v = (t < NBLK) ? g_part[t] : 0;
    s[t] = v;
    __syncthreads();
    for (int off = 1; off < 128; off <<= 1) {
        int a = (t >= off) ? s[t - off] : 0;
        __syncthreads();
        s[t] += a;
        __syncthreads();
    }
    if (t < NBLK) g_part[t] = s[t] - v;     // exclusive block offsets
}

__global__ void scan3_kernel() {
    int i = blockIdx.x * blockDim.x + threadIdx.x;
    if (i < NN) {
        int v = g_rowstart[i] + g_part[i / SCAN_B];
        g_rowstart[i] = v;
        g_cursor[i] = v;
    }
    if (i == 0) g_rowstart[NN] = EE;
}

__global__ void edge_scatter_kernel(const int* __restrict__ src, const int* __restrict__ dst,
                                    const float* __restrict__ ea) {
    int e = blockIdx.x * blockDim.x + threadIdx.x;
    if (e >= EE) return;
    int s = src[e], d = dst[e];
    float w = -g_dinv[s] * ea[e] * g_dinv[d];
    int pos = atomicAdd(&g_cursor[d], 1);
    g_esrc[pos] = s;
    g_ew[pos] = w;
}

// ---------------- vector helpers ----------------
template <int VW> struct VecT;
template <> struct VecT<4> { using T = float4; };
template <> struct VecT<2> { using T = float2; };
template <> struct VecT<1> { using T = float; };

__device__ __forceinline__ float4 vzero4() { return make_float4(0.f,0.f,0.f,0.f); }

__device__ __forceinline__ void vfma(float4& a, float w, float4 v) {
    a.x = fmaf(w, v.x, a.x); a.y = fmaf(w, v.y, a.y);
    a.z = fmaf(w, v.z, a.z); a.w = fmaf(w, v.w, a.w);
}
__device__ __forceinline__ void vfma(float2& a, float w, float2 v) {
    a.x = fmaf(w, v.x, a.x); a.y = fmaf(w, v.y, a.y);
}
__device__ __forceinline__ void vfma(float& a, float w, float v) { a = fmaf(w, v, a); }

__device__ __forceinline__ void vadd(float4& a, float4 b) { a.x+=b.x; a.y+=b.y; a.z+=b.z; a.w+=b.w; }
__device__ __forceinline__ void vadd(float2& a, float2 b) { a.x+=b.x; a.y+=b.y; }
__device__ __forceinline__ void vadd(float& a, float b)   { a += b; }

// a = 2*a + p
__device__ __forceinline__ void vscale2add(float4& a, float4 p) {
    a.x = fmaf(2.f, a.x, p.x); a.y = fmaf(2.f, a.y, p.y);
    a.z = fmaf(2.f, a.z, p.z); a.w = fmaf(2.f, a.w, p.w);
}
__device__ __forceinline__ void vscale2add(float2& a, float2 p) {
    a.x = fmaf(2.f, a.x, p.x); a.y = fmaf(2.f, a.y, p.y);
}
__device__ __forceinline__ void vscale2add(float& a, float p) { a = fmaf(2.f, a, p); }

// a = relu(a + p0 - p2 + b)
__device__ __forceinline__ void vcombine(float4& a, float4 p0, float4 p2, float4 b) {
    a.x = fmaxf(a.x + p0.x - p2.x + b.x, 0.f);
    a.y = fmaxf(a.y + p0.y - p2.y + b.y, 0.f);
    a.z = fmaxf(a.z + p0.z - p2.z + b.z, 0.f);
    a.w = fmaxf(a.w + p0.w - p2.w + b.w, 0.f);
}
__device__ __forceinline__ void vcombine(float2& a, float2 p0, float2 p2, float2 b) {
    a.x = fmaxf(a.x + p0.x - p2.x + b.x, 0.f);
    a.y = fmaxf(a.y + p0.y - p2.y + b.y, 0.f);
}
__device__ __forceinline__ void vcombine(float& a, float p0, float p2, float b) {
    a = fmaxf(a + p0 - p2 + b, 0.f);
}

template <typename V> __device__ __forceinline__ V vz();
template <> __device__ __forceinline__ float4 vz<float4>() { return make_float4(0.f,0.f,0.f,0.f); }
template <> __device__ __forceinline__ float2 vz<float2>() { return make_float2(0.f,0.f); }
template <> __device__ __forceinline__ float  vz<float>()  { return 0.f; }

// ---------------- sparse propagate: warp per node ----------------
// MODEB=false: out[n] = S0[n] + 2 * sum_j w_j * G[src_j]         (Q' = P1 + 2 L P2)
// MODEB=true : out[n] = relu(S0[n] - S1[n] + sum + bias)         (H = relu(P0 - P2 + L Q' + b))
template <int F, bool MODEB>
__global__ void __launch_bounds__(256)
prop_kernel(const float* __restrict__ G, const float* __restrict__ S0,
            const float* __restrict__ S1, const float* __restrict__ bias,
            float* __restrict__ out) {
    constexpr int VW = F / 32;
    using V = typename VecT<VW>::T;
    int node = (blockIdx.x << 3) + (threadIdx.x >> 5);
    if (node >= NN) return;
    int lane = threadIdx.x & 31;
    int s = g_rowstart[node], e = g_rowstart[node + 1];
    const V* G4 = (const V*)G;
    V a0 = vz<V>(), a1 = vz<V>();
    int j = s;
    for (; j + 1 < e; j += 2) {
        vfma(a0, g_ew[j],     G4[(long)g_esrc[j]     * 32 + lane]);
        vfma(a1, g_ew[j + 1], G4[(long)g_esrc[j + 1] * 32 + lane]);
    }
    if (j < e) vfma(a0, g_ew[j], G4[(long)g_esrc[j] * 32 + lane]);
    vadd(a0, a1);
    long o = (long)node * 32 + lane;
    if (!MODEB) {
        V p1 = ((const V*)S0)[o];
        vscale2add(a0, p1);                    // a0 = 2*a0 + P1[n]
    } else {
        V p0 = ((const V*)S0)[o];
        V p2 = ((const V*)S1)[o];
        V b  = ((const V*)bias)[lane];
        vcombine(a0, p0, p2, b);               // relu(a0 + P0 - P2 + b)
    }
    ((V*)out)[o] = a0;
}

// ---------------- tf32 tensor-core GEMM: Pk = A @ W[k], k = blockIdx.y ----------------
__device__ __forceinline__ unsigned f2tf32(float x) {
    unsigned u;
    asm("cvt.rna.tf32.f32 %0, %1;" : "=r"(u) : "f"(x));
    return u;
}

__device__ __forceinline__ void mma_tf32(float* c, const unsigned* a, unsigned b0, unsigned b1) {
    asm volatile(
        "mma.sync.aligned.m16n8k8.row.col.f32.tf32.tf32.f32 "
        "{%0,%1,%2,%3}, {%4,%5,%6,%7}, {%8,%9}, {%0,%1,%2,%3};"
        : "+f"(c[0]), "+f"(c[1]), "+f"(c[2]), "+f"(c[3])
        : "r"(a[0]), "r"(a[1]), "r"(a[2]), "r"(a[3]), "r"(b0), "r"(b1));
}

template <int FIN, int FOUT>
__global__ void __launch_bounds__(256)
gemmP_mma(const float* __restrict__ A, const float* __restrict__ W,
          float* __restrict__ P0, float* __restrict__ P1, float* __restrict__ P2) {
    constexpr int BM = 128, BK = 32, NT = FOUT / 8;
    constexpr int ASTR = 36;
    constexpr int BSTR = FOUT + 8;
    __shared__ unsigned As[BM * ASTR];
    __shared__ unsigned Bs[BK * BSTR];

    int kw = blockIdx.y;
    const float* Wk = W + (long)kw * FIN * FOUT;
    float* out = (kw == 0) ? P0 : ((kw == 1) ? P1 : P2);

    int tid = threadIdx.x;
    int w = tid >> 5, lane = tid & 31;
    int ly = lane >> 2, lx = lane & 3;
    int row0 = blockIdx.x * BM;

    float acc[NT][4];
#pragma unroll
    for (int t = 0; t < NT; t++)
#pragma unroll
        for (int i = 0; i < 4; i++) acc[t][i] = 0.f;

    for (int k0 = 0; k0 < FIN; k0 += BK) {
        // A tile: 128x32 floats = 1024 float4, 4 per thread.
#pragma unroll
        for (int i = 0; i < 4; i++) {
            int idx = i * 256 + tid;
            int r = idx >> 3, k4 = (idx & 7) * 4;
            float4 v = make_float4(0.f, 0.f, 0.f, 0.f);
            int grow = row0 + r;
            if (grow < NN) v = *(const float4*)&A[(long)grow * FIN + k0 + k4];
            As[r * ASTR + k4 + 0] = f2tf32(v.x);
            As[r * ASTR + k4 + 1] = f2tf32(v.y);
            As[r * ASTR + k4 + 2] = f2tf32(v.z);
            As[r * ASTR + k4 + 3] = f2tf32(v.w);
        }
        // B tile: 32 x FOUT from Wk.
#pragma unroll
        for (int i = 0; i < (BK * FOUT / 4 + 255) / 256; i++) {
            int idx = i * 256 + tid;
            if (idx < BK * FOUT / 4) {
                int r = idx / (FOUT / 4);
                int n4 = (idx % (FOUT / 4)) * 4;
                float4 v = *(const float4*)&Wk[(long)(k0 + r) * FOUT + n4];
                Bs[r * BSTR + n4 + 0] = f2tf32(v.x);
                Bs[r * BSTR + n4 + 1] = f2tf32(v.y);
                Bs[r * BSTR + n4 + 2] = f2tf32(v.z);
                Bs[r * BSTR + n4 + 3] = f2tf32(v.w);
            }
        }
        __syncthreads();
#pragma unroll
        for (int c = 0; c < 4; c++) {
            unsigned a[4];
            int ar = w * 16 + ly;
            int ak = c * 8 + lx;
            a[0] = As[ar * ASTR + ak];
            a[1] = As[(ar + 8) * ASTR + ak];
            a[2] = As[ar * ASTR + ak + 4];
            a[3] = As[(ar + 8) * ASTR + ak + 4];
#pragma unroll
            for (int t = 0; t < NT; t++) {
                int bn = t * 8 + ly;
                unsigned b0 = Bs[(c * 8 + lx) * BSTR + bn];
                unsigned b1 = Bs[(c * 8 + lx + 4) * BSTR + bn];
                mma_tf32(acc[t], a, b0, b1);
            }
        }
        __syncthreads();
    }
    int r0 = row0 + w * 16 + ly;
#pragma unroll
    for (int t = 0; t < NT; t++) {
        int col = t * 8 + lx * 2;
        if (r0 < NN)
            *(float2*)&out[(long)r0 * FOUT + col] = make_float2(acc[t][0], acc[t][1]);
        if (r0 + 8 < NN)
            *(float2*)&out[(long)(r0 + 8) * FOUT + col] = make_float2(acc[t][2], acc[t][3]);
    }
}

// ---------------- pooling (batch sorted -> run-length local accumulation) ----------------
#define POOL_NPB 256
__global__ void __launch_bounds__(256)
pool_kernel(const int* __restrict__ batch) {
    int t = threadIdx.x;
    int f = t & 31;
    int sub = t >> 5;   // 0..7
    int g_cur = -1;
    float acc = 0.f, cnt = 0.f;
    for (int i = 0; i < POOL_NPB / 8; i++) {
        int n = blockIdx.x * POOL_NPB + sub + i * 8;
        if (n >= NN) break;
        int g = batch[n];
        if (g != g_cur) {
            if (g_cur >= 0) {
                atomicAdd(&g_pool[g_cur * 32 + f], acc);
                if (f == 0) atomicAdd(&g_cntg[g_cur], cnt);
            }
            g_cur = g; acc = 0.f; cnt = 0.f;
        }
        acc += g_H3[(long)n * 32 + f];
        cnt += 1.f;
    }
    if (g_cur >= 0) {
        atomicAdd(&g_pool[g_cur * 32 + f], acc);
        if (f == 0) atomicAdd(&g_cntg[g_cur], cnt);
    }
}

__global__ void final_kernel(const float* __restrict__ Wl, const float* __restrict__ bl,
                             float* __restrict__ out) {
    int t = threadIdx.x;
    if (t >= GG * 2) return;
    int g = t >> 1, c = t & 1;
    float cnt = fmaxf(g_cntg[g], 1.f);
    float inv = 1.f / cnt;
    float s = bl[c];
#pragma unroll
    for (int f = 0; f < 32; f++) s += (g_pool[g * 32 + f] * inv) * Wl[f * 2 + c];
    out[g * 2 + c] = s;
}

// ---------------- driver ----------------
extern "C" void kernel_launch(void* const* d_in, const int* in_sizes, int n_in,
                              void* d_out, int out_size) {
    const float* x     = (const float*)d_in[0];
    const int*   ei    = (const int*)d_in[1];
    const float* ea    = (const float*)d_in[2];
    const int*   batch = (const int*)d_in[3];
    const float* W1 = (const float*)d_in[4];
    const float* b1 = (const float*)d_in[5];
    const float* W2 = (const float*)d_in[6];
    const float* b2 = (const float*)d_in[7];
    const float* W3 = (const float*)d_in[8];
    const float* b3 = (const float*)d_in[9];
    const float* Wl = (const float*)d_in[10];
    const float* bl = (const float*)d_in[11];
    float* out = (float*)d_out;

    const int* src = ei;
    const int* dst = ei + EE;

    float *P0, *P1, *P2, *H1, *H2, *H3;
    cudaGetSymbolAddress((void**)&P0, g_P0);
    cudaGetSymbolAddress((void**)&P1, g_P1);
    cudaGetSymbolAddress((void**)&P2, g_P2);
    cudaGetSymbolAddress((void**)&H1, g_H1);
    cudaGetSymbolAddress((void**)&H2, g_H2);
    cudaGetSymbolAddress((void**)&H3, g_H3);

    int nb = (NN + 255) / 256;
    int eb = (EE + 255) / 256;
    int pb = (NN + 7) / 8;                 // warp-per-node prop grid
    dim3 gg((NN + 127) / 128, 3);          // gemm grid (y = weight index k)

    zero_kernel<<<nb, 256>>>();
    edge_deg_kernel<<<eb, 256>>>(src, dst, ea);
    dinv_kernel<<<nb, 256>>>();
    scan1_kernel<<<NBLK, SCAN_B>>>();
    scan2_kernel<<<1, 128>>>();
    scan3_kernel<<<nb, 256>>>();
    edge_scatter_kernel<<<eb, 256>>>(src, dst, ea);

    // Layer 1: 160 -> 128.  Pk = x@W1[k]; Q'=P1+2LP2 (in place); H1=relu(P0-P2+LQ'+b1)
    gemmP_mma<160, 128><<<gg, 256>>>(x, W1, P0, P1, P2);
    prop_kernel<128, false><<<pb, 256>>>(P2, P1, nullptr, nullptr, P1);
    prop_kernel<128, true ><<<pb, 256>>>(P1, P0, P2, b1, H1);

    // Layer 2: 128 -> 64
    gemmP_mma<128, 64><<<gg, 256>>>(H1, W2, P0, P1, P2);
    prop_kernel<64, false><<<pb, 256>>>(P2, P1, nullptr, nullptr, P1);
    prop_kernel<64, true ><<<pb, 256>>>(P1, P0, P2, b2, H2);

    // Layer 3: 64 -> 32
    gemmP_mma<64, 32><<<gg, 256>>>(H2, W3, P0, P1, P2);
    prop_kernel<32, false><<<pb, 256>>>(P2, P1, nullptr, nullptr, P1);
    prop_kernel<32, true ><<<pb, 256>>>(P1, P0, P2, b3, H3);

    // Pool + linear
    pool_kernel<<<(NN + POOL_NPB - 1) / POOL_NPB, 256>>>(batch);
    final_kernel<<<1, 256>>>(Wl, bl, out);
}

// round 5
// speedup vs baseline: 1.0909x; 1.0909x over previous
#include <cuda_runtime.h>
#include <cuda_bf16.h>

#define NN 50000
#define EE 500000
#define GG 128
#define SCAN_B 512
#define NBLK ((NN + SCAN_B - 1) / SCAN_B)   // 98

struct __align__(8) Edge { int s; float w; };

// ---------------- scratch (static device allocations) ----------------
__device__ float g_deg[NN];
__device__ float g_dinv[NN];
__device__ int   g_count[NN];
__device__ int   g_rowstart[NN + 1];
__device__ int   g_cursor[NN];
__device__ int   g_part[NBLK];
__device__ Edge  g_edge[EE];

__device__ float g_T1[NN * 160];
__device__ float g_T2[NN * 160];
__device__ float g_H1[NN * 128];
__device__ float g_H2[NN * 64];
__device__ float g_pool[GG * 32];
__device__ float g_cntg[GG];

// ---------------- preprocessing ----------------
__global__ void zero_kernel() {
    int i = blockIdx.x * blockDim.x + threadIdx.x;
    if (i < NN) { g_deg[i] = 0.f; g_count[i] = 0; }
    if (i < GG * 32) g_pool[i] = 0.f;
    if (i < GG) g_cntg[i] = 0.f;
}

__global__ void edge_deg_kernel(const int* __restrict__ src, const int* __restrict__ dst,
                                const float* __restrict__ ea) {
    int e = blockIdx.x * blockDim.x + threadIdx.x;
    if (e >= EE) return;
    atomicAdd(&g_deg[src[e]], ea[e]);
    atomicAdd(&g_count[dst[e]], 1);
}

__global__ void scan1_kernel() {
    __shared__ int s[SCAN_B];
    int t = threadIdx.x;
    int i = blockIdx.x * SCAN_B + t;
    int v = (i < NN) ? g_count[i] : 0;
    s[t] = v;
    __syncthreads();
    for (int off = 1; off < SCAN_B; off <<= 1) {
        int add = (t >= off) ? s[t - off] : 0;
        __syncthreads();
        s[t] += add;
        __syncthreads();
    }
    if (i < NN) g_rowstart[i] = s[t] - v;   // exclusive within block
    if (t == SCAN_B - 1) g_part[blockIdx.x] = s[t];
}

__global__ void scan2_kernel() {
    __shared__ int s[128];
    int t = threadIdx.x;
    int v = (t < NBLK) ? g_part[t] : 0;
    s[t] = v;
    __syncthreads();
    for (int off = 1; off < 128; off <<= 1) {
        int a = (t >= off) ? s[t - off] : 0;
        __syncthreads();
        s[t] += a;
        __syncthreads();
    }
    if (t < NBLK) g_part[t] = s[t] - v;     // exclusive block offsets
}

// scan3 + dinv + per-graph node count (fused)
__global__ void scan3_kernel(const int* __restrict__ batch) {
    int i = blockIdx.x * blockDim.x + threadIdx.x;
    if (i < NN) {
        int v = g_rowstart[i] + g_part[i / SCAN_B];
        g_rowstart[i] = v;
        g_cursor[i] = v;
        float d = g_deg[i];
        g_dinv[i] = (d > 0.f) ? rsqrtf(d) : 0.f;
        atomicAdd(&g_cntg[batch[i]], 1.f);
    }
    if (i == 0) g_rowstart[NN] = EE;
}

__global__ void edge_scatter_kernel(const int* __restrict__ src, const int* __restrict__ dst,
                                    const float* __restrict__ ea) {
    int e = blockIdx.x * blockDim.x + threadIdx.x;
    if (e >= EE) return;
    int s = src[e], d = dst[e];
    float w = -g_dinv[s] * ea[e] * g_dinv[d];
    int pos = atomicAdd(&g_cursor[d], 1);
    Edge eg; eg.s = s; eg.w = w;
    g_edge[pos] = eg;
}

// ---------------- vector helpers ----------------
template <int VW> struct VecT;
template <> struct VecT<4> { using T = float4; };
template <> struct VecT<2> { using T = float2; };

__device__ __forceinline__ void vfma(float4& a, float w, float4 v) {
    a.x = fmaf(w, v.x, a.x); a.y = fmaf(w, v.y, a.y);
    a.z = fmaf(w, v.z, a.z); a.w = fmaf(w, v.w, a.w);
}
__device__ __forceinline__ void vfma(float2& a, float w, float2 v) {
    a.x = fmaf(w, v.x, a.x); a.y = fmaf(w, v.y, a.y);
}
__device__ __forceinline__ void vadd(float4& a, float4 b) { a.x+=b.x; a.y+=b.y; a.z+=b.z; a.w+=b.w; }
__device__ __forceinline__ void vadd(float2& a, float2 b) { a.x+=b.x; a.y+=b.y; }
__device__ __forceinline__ void vs2s(float4& a, float4 t) {  // a = 2a - t
    a.x = fmaf(2.f,a.x,-t.x); a.y = fmaf(2.f,a.y,-t.y);
    a.z = fmaf(2.f,a.z,-t.z); a.w = fmaf(2.f,a.w,-t.w);
}
__device__ __forceinline__ void vs2s(float2& a, float2 t) {
    a.x = fmaf(2.f,a.x,-t.x); a.y = fmaf(2.f,a.y,-t.y);
}
template <typename V> __device__ __forceinline__ V vz();
template <> __device__ __forceinline__ float4 vz<float4>() { return make_float4(0.f,0.f,0.f,0.f); }
template <> __device__ __forceinline__ float2 vz<float2>() { return make_float2(0.f,0.f); }

// ---------------- sparse propagate: warp per node, 4-way ILP ----------------
// F=160: lane covers float4 idx lane, plus lane+32 for lane<8.
template <bool SECOND>
__global__ void __launch_bounds__(256)
prop160_kernel(const float* __restrict__ X, const float* __restrict__ T0,
               float* __restrict__ out) {
    int node = (blockIdx.x << 3) + (threadIdx.x >> 5);
    if (node >= NN) return;
    int lane = threadIdx.x & 31;
    int s = g_rowstart[node], e = g_rowstart[node + 1];
    const float4* X4 = (const float4*)X;
    float4 a0 = vz<float4>(), a1 = a0, a2 = a0, a3 = a0;
    float4 b0 = a0, b1 = a0, b2 = a0, b3 = a0;
    int j = s;
    for (; j + 3 < e; j += 4) {
        Edge e0 = g_edge[j], e1 = g_edge[j+1], e2 = g_edge[j+2], e3 = g_edge[j+3];
        long r0 = (long)e0.s * 40, r1 = (long)e1.s * 40, r2 = (long)e2.s * 40, r3 = (long)e3.s * 40;
        vfma(a0, e0.w, X4[r0 + lane]);
        vfma(a1, e1.w, X4[r1 + lane]);
        vfma(a2, e2.w, X4[r2 + lane]);
        vfma(a3, e3.w, X4[r3 + lane]);
        if (lane < 8) {
            vfma(b0, e0.w, X4[r0 + 32 + lane]);
            vfma(b1, e1.w, X4[r1 + 32 + lane]);
            vfma(b2, e2.w, X4[r2 + 32 + lane]);
            vfma(b3, e3.w, X4[r3 + 32 + lane]);
        }
    }
    for (; j < e; j++) {
        Edge e0 = g_edge[j];
        long r0 = (long)e0.s * 40;
        vfma(a0, e0.w, X4[r0 + lane]);
        if (lane < 8) vfma(b0, e0.w, X4[r0 + 32 + lane]);
    }
    vadd(a0, a1); vadd(a2, a3); vadd(a0, a2);
    vadd(b0, b1); vadd(b2, b3); vadd(b0, b2);
    long o = (long)node * 40;
    if (SECOND) {
        vs2s(a0, ((const float4*)T0)[o + lane]);
        if (lane < 8) vs2s(b0, ((const float4*)T0)[o + 32 + lane]);
    }
    ((float4*)out)[o + lane] = a0;
    if (lane < 8) ((float4*)out)[o + 32 + lane] = b0;
}

// F = 128 (float4) or 64 (float2): one vector per lane.
template <int F, bool SECOND>
__global__ void __launch_bounds__(256)
prop_kernel(const float* __restrict__ X, const float* __restrict__ T0,
            float* __restrict__ out) {
    using V = typename VecT<F / 32>::T;
    int node = (blockIdx.x << 3) + (threadIdx.x >> 5);
    if (node >= NN) return;
    int lane = threadIdx.x & 31;
    int s = g_rowstart[node], e = g_rowstart[node + 1];
    const V* X4 = (const V*)X;
    V a0 = vz<V>(), a1 = a0, a2 = a0, a3 = a0;
    int j = s;
    for (; j + 3 < e; j += 4) {
        Edge e0 = g_edge[j], e1 = g_edge[j+1], e2 = g_edge[j+2], e3 = g_edge[j+3];
        vfma(a0, e0.w, X4[(long)e0.s * 32 + lane]);
        vfma(a1, e1.w, X4[(long)e1.s * 32 + lane]);
        vfma(a2, e2.w, X4[(long)e2.s * 32 + lane]);
        vfma(a3, e3.w, X4[(long)e3.s * 32 + lane]);
    }
    for (; j < e; j++) {
        Edge e0 = g_edge[j];
        vfma(a0, e0.w, X4[(long)e0.s * 32 + lane]);
    }
    vadd(a0, a1); vadd(a2, a3); vadd(a0, a2);
    long o = (long)node * 32 + lane;
    if (SECOND) vs2s(a0, ((const V*)T0)[o]);
    ((V*)out)[o] = a0;
}

// ---------------- tf32 tensor-core fused 3-term GEMM (reg double-buffered) ----------------
__device__ __forceinline__ unsigned f2tf32(float x) {
    unsigned u;
    asm("cvt.rna.tf32.f32 %0, %1;" : "=r"(u) : "f"(x));
    return u;
}

__device__ __forceinline__ void mma_tf32(float* c, const unsigned* a, unsigned b0, unsigned b1) {
    asm volatile(
        "mma.sync.aligned.m16n8k8.row.col.f32.tf32.tf32.f32 "
        "{%0,%1,%2,%3}, {%4,%5,%6,%7}, {%8,%9}, {%0,%1,%2,%3};"
        : "+f"(c[0]), "+f"(c[1]), "+f"(c[2]), "+f"(c[3])
        : "r"(a[0]), "r"(a[1]), "r"(a[2]), "r"(a[3]), "r"(b0), "r"(b1));
}

// out = relu([A0|A1|A2] @ W + bias); if POOL, atomically accumulate into g_pool by batch.
template <int FIN, int FOUT, bool POOL>
__global__ void __launch_bounds__(256)
gemm3_mma(const float* __restrict__ A0, const float* __restrict__ A1,
          const float* __restrict__ A2, const float* __restrict__ W,
          const float* __restrict__ bias, float* __restrict__ out,
          const int* __restrict__ batch) {
    constexpr int BM = 128, BK = 32;
    constexpr int ASTR = 36, BSTR = FOUT + 8;
    constexpr int NCH = 3 * FIN / BK;
    constexpr int BLD = (BK * FOUT / 4) / 256;  // B float4 per thread
    constexpr int NI = FOUT / 16;               // n8 tiles per warp (warp tile 32 x FOUT/2)
    __shared__ unsigned As[BM * ASTR];
    __shared__ unsigned Bs[BK * BSTR];

    int tid = threadIdx.x;
    int w = tid >> 5, lane = tid & 31;
    int wy = w >> 1, wx = w & 1;
    int ly = lane >> 2, lx = lane & 3;
    int row0 = blockIdx.x * BM;

    float4 ar[4];
    float4 br[BLD];

    float acc[2][NI][4];
#pragma unroll
    for (int mi = 0; mi < 2; mi++)
#pragma unroll
        for (int ni = 0; ni < NI; ni++)
#pragma unroll
            for (int i = 0; i < 4; i++) acc[mi][ni][i] = 0.f;

    // ---- load chunk 0 into registers ----
    {
        const float* A = A0;
#pragma unroll
        for (int i = 0; i < 4; i++) {
            int idx = i * 256 + tid;
            int r = idx >> 3, k4 = (idx & 7) * 4;
            int grow = row0 + r;
            ar[i] = (grow < NN) ? *(const float4*)&A[(long)grow * FIN + k4]
                                : make_float4(0.f, 0.f, 0.f, 0.f);
        }
#pragma unroll
        for (int i = 0; i < BLD; i++) {
            int idx = i * 256 + tid;
            int rB = idx / (FOUT / 4);
            int n4 = (idx % (FOUT / 4)) * 4;
            br[i] = *(const float4*)&W[(long)rB * FOUT + n4];
        }
    }

    for (int c = 0; c < NCH; c++) {
        // ---- store current chunk (with tf32 cvt) to smem ----
#pragma unroll
        for (int i = 0; i < 4; i++) {
            int idx = i * 256 + tid;
            int r = idx >> 3, k4 = (idx & 7) * 4;
            uint4 u;
            u.x = f2tf32(ar[i].x); u.y = f2tf32(ar[i].y);
            u.z = f2tf32(ar[i].z); u.w = f2tf32(ar[i].w);
            *(uint4*)&As[r * ASTR + k4] = u;
        }
#pragma unroll
        for (int i = 0; i < BLD; i++) {
            int idx = i * 256 + tid;
            int rB = idx / (FOUT / 4);
            int n4 = (idx % (FOUT / 4)) * 4;
            uint4 u;
            u.x = f2tf32(br[i].x); u.y = f2tf32(br[i].y);
            u.z = f2tf32(br[i].z); u.w = f2tf32(br[i].w);
            *(uint4*)&Bs[rB * BSTR + n4] = u;
        }
        __syncthreads();

        // ---- prefetch next chunk into registers (overlaps MMAs) ----
        if (c + 1 < NCH) {
            int k0 = (c + 1) * BK;
            const float* A = (k0 < FIN) ? A0 : ((k0 < 2 * FIN) ? A1 : A2);
            int kk = k0 % FIN;
#pragma unroll
            for (int i = 0; i < 4; i++) {
                int idx = i * 256 + tid;
                int r = idx >> 3, k4 = (idx & 7) * 4;
                int grow = row0 + r;
                ar[i] = (grow < NN) ? *(const float4*)&A[(long)grow * FIN + kk + k4]
                                    : make_float4(0.f, 0.f, 0.f, 0.f);
            }
#pragma unroll
            for (int i = 0; i < BLD; i++) {
                int idx = i * 256 + tid;
                int rB = idx / (FOUT / 4);
                int n4 = (idx % (FOUT / 4)) * 4;
                br[i] = *(const float4*)&W[(long)(k0 + rB) * FOUT + n4];
            }
        }

        // ---- MMAs on current chunk ----
#pragma unroll
        for (int cc = 0; cc < 4; cc++) {
            unsigned a[2][4];
#pragma unroll
            for (int mi = 0; mi < 2; mi++) {
                int arow = wy * 32 + mi * 16 + ly;
                int ak = cc * 8 + lx;
                a[mi][0] = As[arow * ASTR + ak];
                a[mi][1] = As[(arow + 8) * ASTR + ak];
                a[mi][2] = As[arow * ASTR + ak + 4];
                a[mi][3] = As[(arow + 8) * ASTR + ak + 4];
            }
#pragma unroll
            for (int ni = 0; ni < NI; ni++) {
                int bn = wx * (FOUT / 2) + ni * 8 + ly;
                unsigned b0 = Bs[(cc * 8 + lx) * BSTR + bn];
                unsigned b1 = Bs[(cc * 8 + lx + 4) * BSTR + bn];
                mma_tf32(acc[0][ni], a[0], b0, b1);
                mma_tf32(acc[1][ni], a[1], b0, b1);
            }
        }
        __syncthreads();
    }

    // ---- epilogue ----
#pragma unroll
    for (int mi = 0; mi < 2; mi++) {
        int r0 = row0 + wy * 32 + mi * 16 + ly;
#pragma unroll
        for (int ni = 0; ni < NI; ni++) {
            int col = wx * (FOUT / 2) + ni * 8 + lx * 2;
            float bv0 = bias[col], bv1 = bias[col + 1];
            float v00 = fmaxf(acc[mi][ni][0] + bv0, 0.f);
            float v01 = fmaxf(acc[mi][ni][1] + bv1, 0.f);
            float v10 = fmaxf(acc[mi][ni][2] + bv0, 0.f);
            float v11 = fmaxf(acc[mi][ni][3] + bv1, 0.f);
            if (!POOL) {
                if (r0 < NN)     *(float2*)&out[(long)r0 * FOUT + col] = make_float2(v00, v01);
                if (r0 + 8 < NN) *(float2*)&out[(long)(r0 + 8) * FOUT + col] = make_float2(v10, v11);
            } else {
                if (r0 < NN) {
                    int g = batch[r0];
                    atomicAdd(&g_pool[g * 32 + col], v00);
                    atomicAdd(&g_pool[g * 32 + col + 1], v01);
                }
                if (r0 + 8 < NN) {
                    int g = batch[r0 + 8];
                    atomicAdd(&g_pool[g * 32 + col], v10);
                    atomicAdd(&g_pool[g * 32 + col + 1], v11);
                }
            }
        }
    }
}

// ---------------- final linear ----------------
__global__ void final_kernel(const float* __restrict__ Wl, const float* __restrict__ bl,
                             float* __restrict__ out) {
    int t = threadIdx.x;
    if (t >= GG * 2) return;
    int g = t >> 1, c = t & 1;
    float cnt = fmaxf(g_cntg[g], 1.f);
    float inv = 1.f / cnt;
    float s = bl[c];
#pragma unroll
    for (int f = 0; f < 32; f++) s += (g_pool[g * 32 + f] * inv) * Wl[f * 2 + c];
    out[g * 2 + c] = s;
}

// ---------------- driver ----------------
extern "C" void kernel_launch(void* const* d_in, const int* in_sizes, int n_in,
                              void* d_out, int out_size) {
    const float* x     = (const float*)d_in[0];
    const int*   ei    = (const int*)d_in[1];
    const float* ea    = (const float*)d_in[2];
    const int*   batch = (const int*)d_in[3];
    const float* W1 = (const float*)d_in[4];
    const float* b1 = (const float*)d_in[5];
    const float* W2 = (const float*)d_in[6];
    const float* b2 = (const float*)d_in[7];
    const float* W3 = (const float*)d_in[8];
    const float* b3 = (const float*)d_in[9];
    const float* Wl = (const float*)d_in[10];
    const float* bl = (const float*)d_in[11];
    float* out = (float*)d_out;

    const int* src = ei;
    const int* dst = ei + EE;

    float *T1, *T2, *H1, *H2;
    cudaGetSymbolAddress((void**)&T1, g_T1);
    cudaGetSymbolAddress((void**)&T2, g_T2);
    cudaGetSymbolAddress((void**)&H1, g_H1);
    cudaGetSymbolAddress((void**)&H2, g_H2);

    int nb = (NN + 255) / 256;
    int eb = (EE + 255) / 256;
    int pb = (NN + 7) / 8;            // warp-per-node prop grid
    int gb = (NN + 127) / 128;        // gemm grid

    zero_kernel<<<nb, 256>>>();
    edge_deg_kernel<<<eb, 256>>>(src, dst, ea);
    scan1_kernel<<<NBLK, SCAN_B>>>();
    scan2_kernel<<<1, 128>>>();
    scan3_kernel<<<nb, 256>>>(batch);
    edge_scatter_kernel<<<eb, 256>>>(src, dst, ea);

    // Layer 1: 160 -> 128
    prop160_kernel<false><<<pb, 256>>>(x, nullptr, T1);
    prop160_kernel<true ><<<pb, 256>>>(T1, x, T2);
    gemm3_mma<160, 128, false><<<gb, 256>>>(x, T1, T2, W1, b1, H1, nullptr);

    // Layer 2: 128 -> 64
    prop_kernel<128, false><<<pb, 256>>>(H1, nullptr, T1);
    prop_kernel<128, true ><<<pb, 256>>>(T1, H1, T2);
    gemm3_mma<128, 64, false><<<gb, 256>>>(H1, T1, T2, W2, b2, H2, nullptr);

    // Layer 3: 64 -> 32  (pooling fused into epilogue)
    prop_kernel<64, false><<<pb, 256>>>(H2, nullptr, T1);
    prop_kernel<64, true ><<<pb, 256>>>(T1, H2, T2);
    gemm3_mma<64, 32, true><<<gb, 256>>>(H2, T1, T2, W3, b3, nullptr, batch);

    // Final linear
    final_kernel<<<1, 256>>>(Wl, bl, out);
}